// round 13
// baseline (speedup 1.0000x reference)
#include <cuda_runtime.h>
#include <cuda_fp16.h>

// GaussianSoftmax: X[8,4096,16], sigma[1] -> softmax(exp(exp(-sqdist/sigma)), axis=2) [8,4096,4096]
//
// R13 = R10's barrier-free direct-LDG mainloop at DOUBLE the warps:
//  T=256, thread = 4 rows x 2 cols (xq = 8fp x 4r = 64 regs -> ~115 total, no spill),
//  CTA = 8 rows via two 4-row thread groups; 2 CTAs/SM -> 16 warps/SM for latency
//  hiding (replaces the register-hungry prefetch that failed R11/R12).
//  xj read directly from L2-resident pre-transposed g_xt via LDG.128; h fp16 in smem;
//  3 syncthreads total; streaming STG.128 out.

#define BB 8
#define NN 4096
#define FF 16
#define RR 8
#define TT 256
#define NK 16                     // k-steps of 256 cols (2 per thread)
#define L2E  1.4426950408889634f
#define C528 0.5287663729448977f  // log2(log2(e))

typedef unsigned long long ull;

__device__ float g_sqc[BB * NN];      // cexp * ||x_j||^2
__device__ float g_xt[BB * FF * NN];  // [b][fp][j] float2

// smem: hbuf uint[8][2048] = 64KB (uint m = cols 2m,2m+1), part, inv
#define HBUF_OFF 0
#define PART_OFF 65536                 // 8 warps x 4 floats
#define INV_OFF  (PART_OFF + 128)
#define SMEM_TOTAL (INV_OFF + 32)

__device__ __forceinline__ ull ffma2(ull a, ull b, ull c) {
    ull d; asm("fma.rn.f32x2 %0, %1, %2, %3;" : "=l"(d) : "l"(a), "l"(b), "l"(c)); return d;
}
__device__ __forceinline__ float2 upk(ull v) {
    float2 r; asm("mov.b64 {%0, %1}, %2;" : "=f"(r.x), "=f"(r.y) : "l"(v)); return r;
}
__device__ __forceinline__ float ex2f(float x) {
    float r; asm("ex2.approx.f32 %0, %1;" : "=f"(r) : "f"(x)); return r;
}
__device__ __forceinline__ unsigned pkh2(float a, float b) {
    __half2 h = __floats2half2_rn(a, b);
    return *reinterpret_cast<unsigned*>(&h);
}
__device__ __forceinline__ void stcs4(float* p, float4 v) {
    asm volatile("st.global.cs.v4.f32 [%0], {%1, %2, %3, %4};"
                 :: "l"(p), "f"(v.x), "f"(v.y), "f"(v.z), "f"(v.w) : "memory");
}
__device__ __forceinline__ ulonglong2 ldg_nc128(const ulonglong2* p) {
    ulonglong2 v;
    asm("ld.global.nc.v2.b64 {%0, %1}, [%2];" : "=l"(v.x), "=l"(v.y) : "l"(p));
    return v;
}

// ---- pre-kernel: transpose X into f-pair rows + cexp*||x_j||^2 ----
__global__ void __launch_bounds__(256)
prep_kernel(const float* __restrict__ X, const float* __restrict__ sigma) {
    int idx = blockIdx.x * 256 + threadIdx.x;          // b*4096 + j
    int b = idx >> 12, j = idx & 4095;
    const float4* p = reinterpret_cast<const float4*>(X) + (size_t)idx * 4;
    float s = 0.f;
    float2* xtb = reinterpret_cast<float2*>(&g_xt[b * 65536]) + j;
    #pragma unroll
    for (int q = 0; q < 4; ++q) {
        float4 v = p[q];
        s += v.x * v.x + v.y * v.y + v.z * v.z + v.w * v.w;
        xtb[(2 * q + 0) * 4096] = make_float2(v.x, v.y);
        xtb[(2 * q + 1) * 4096] = make_float2(v.z, v.w);
    }
    g_sqc[idx] = (-L2E / sigma[0]) * s;
}

__global__ void __launch_bounds__(TT, 2)
GaussianSoftmax_67714454389333_kernel(const float* __restrict__ X,
                                      const float* __restrict__ sigma,
                                      float* __restrict__ out) {
    extern __shared__ char smem_raw[];
    unsigned* hbuf = reinterpret_cast<unsigned*>(smem_raw + HBUF_OFF);  // [8][2048]

    const int tid = threadIdx.x;
    const int b = blockIdx.y;
    const int i0 = blockIdx.x * RR;
    const int rg = tid >> 7;           // row-group 0/1 -> rows rg*4..rg*4+3
    const int ct = tid & 127;          // col-thread within group
    const int rg4 = rg * 4;

    const float* Xb = X + (size_t)b * NN * FF;

    const float sg = sigma[0];
    const float cexp = -L2E / sg;
    const float CM2s = -2.0f * cexp;

    // ---- xq: f-paired xi in regs for my 4 rows (64 regs) + sic ----
    ull xq[8][4];
    float sic[4];
    #pragma unroll
    for (int r = 0; r < 4; ++r) {
        float s = 0.f;
        #pragma unroll
        for (int fp = 0; fp < 8; ++fp) {
            float2 v = *reinterpret_cast<const float2*>(
                &Xb[(size_t)(i0 + rg4 + r) * FF + fp * 2]);
            s = fmaf(v.x, v.x, s);
            s = fmaf(v.y, v.y, s);
            xq[fp][r] = *reinterpret_cast<const ull*>(&v);
        }
        sic[r] = fmaf(cexp, s, C528);
    }

    // xt viewed as ulonglong2[fp][2048] per batch: one LDG.128 = 2 cols x 1 f-pair
    const ulonglong2* xt2 =
        reinterpret_cast<const ulonglong2*>(g_xt) + (size_t)b * 16384;
    const float2* sq2 = reinterpret_cast<const float2*>(g_sqc) + b * 2048;

    float rsum[4] = {0.f, 0.f, 0.f, 0.f};

    // ---- barrier-free mainloop: 16 steps x (4 rows x 2 cols) ----
    #pragma unroll 1
    for (int k = 0; k < NK; ++k) {
        const int m = k * 128 + ct;      // my col-pair index (cols 2m, 2m+1)

        // loads (L2-resident; 16 warps/SM hide latency)
        ull accA[4] = {0, 0, 0, 0};
        ull accB[4] = {0, 0, 0, 0};
        #pragma unroll
        for (int fp = 0; fp < 8; ++fp) {
            ulonglong2 xj = ldg_nc128(xt2 + fp * 2048 + m);
            #pragma unroll
            for (int r = 0; r < 4; ++r) {
                accA[r] = ffma2(xj.x, xq[fp][r], accA[r]);
                accB[r] = ffma2(xj.y, xq[fp][r], accB[r]);
            }
        }
        float2 sj = __ldg(sq2 + m);

        // epilogue: e = CM2s*dot + (sic[r]+sj) ; h = 2^(2^e) ; fp16 h to smem
        #pragma unroll
        for (int r = 0; r < 4; ++r) {
            float base = sic[r];
            float2 aA = upk(accA[r]);
            float2 aB = upk(accB[r]);
            float eA = fmaf(CM2s, aA.x + aA.y, base + sj.x);
            float eB = fmaf(CM2s, aB.x + aB.y, base + sj.y);
            float hA = ex2f(ex2f(eA));
            float hB = ex2f(ex2f(eB));
            rsum[r] += hA + hB;
            hbuf[(rg4 + r) * 2048 + m] = pkh2(hA, hB);  // cols 2m, 2m+1
        }
    }

    // ---- row-sum reduction (8 warps x 4 rows) ----
    float* part = reinterpret_cast<float*>(smem_raw + PART_OFF);   // [8][4]
    #pragma unroll
    for (int r = 0; r < 4; ++r) {
        float v = rsum[r];
        v += __shfl_xor_sync(0xffffffffu, v, 16);
        v += __shfl_xor_sync(0xffffffffu, v, 8);
        v += __shfl_xor_sync(0xffffffffu, v, 4);
        v += __shfl_xor_sync(0xffffffffu, v, 2);
        v += __shfl_xor_sync(0xffffffffu, v, 1);
        if ((tid & 31) == 0) part[(tid >> 5) * 4 + r] = v;
    }
    __syncthreads();
    float* invp = reinterpret_cast<float*>(smem_raw + INV_OFF);
    if (tid < RR) {
        int g = (tid >> 2) * 4, rl = tid & 3;    // row = 4*(tid>>2)... map: warps 0-3 = rows 0-3, warps 4-7 = rows 4-7
        float s = part[(g + 0) * 4 + rl] + part[(g + 1) * 4 + rl] +
                  part[(g + 2) * 4 + rl] + part[(g + 3) * 4 + rl];
        invp[(g >> 2) * 4 + rl] = 1.0f / s;
    }
    __syncthreads();

    // ---- phase 2: normalize fp16 h -> two STG.128 per uint4 (8 contig cols) ----
    float* outB = out + ((size_t)b * NN + i0) * NN;
    const uint4* h4 = reinterpret_cast<const uint4*>(hbuf);        // [8][512]
    #pragma unroll 4
    for (int it = 0; it < 16; ++it) {
        int c4 = it * TT + tid;          // 0..4095
        int r = c4 >> 9;
        int w = c4 & 511;                // 8-col group within row
        float inv = invp[r];
        uint4 v = h4[c4];
        float2 p0 = __half22float2(*reinterpret_cast<__half2*>(&v.x));
        float2 p1 = __half22float2(*reinterpret_cast<__half2*>(&v.y));
        float2 p2 = __half22float2(*reinterpret_cast<__half2*>(&v.z));
        float2 p3 = __half22float2(*reinterpret_cast<__half2*>(&v.w));
        float4 oA = make_float4(p0.x * inv, p0.y * inv, p1.x * inv, p1.y * inv);
        float4 oB = make_float4(p2.x * inv, p2.y * inv, p3.x * inv, p3.y * inv);
        float* po = outB + (size_t)r * NN + w * 8;
        stcs4(po, oA);
        stcs4(po + 4, oB);
    }
}

extern "C" void kernel_launch(void* const* d_in, const int* in_sizes, int n_in,
                              void* d_out, int out_size) {
    const float* X = (const float*)d_in[0];
    const float* sigma = (const float*)d_in[1];
    float* out = (float*)d_out;

    prep_kernel<<<BB * NN / 256, 256>>>(X, sigma);

    cudaFuncSetAttribute(GaussianSoftmax_67714454389333_kernel,
                         cudaFuncAttributeMaxDynamicSharedMemorySize, SMEM_TOTAL);
    dim3 grid(NN / RR, BB);   // (512, 8)
    GaussianSoftmax_67714454389333_kernel<<<grid, TT, SMEM_TOTAL>>>(X, sigma, out);
}

// round 15
// speedup vs baseline: 1.3364x; 1.3364x over previous
#include <cuda_runtime.h>
#include <cuda_fp16.h>

// GaussianSoftmax: X[8,4096,16], sigma[1] -> softmax(exp(exp(-sqdist/sigma)), axis=2) [8,4096,4096]
//
// R14 = R10 with the loop manually ROTATED: loads(k) -> epilogue(k-1) -> dot(k).
// The previous step's epilogue (~70 inst, 16 long-latency MUFUs) fills the ~250cyc
// L2 load-wait window -- at ZERO extra registers (single buf[8], single acc set;
// unlike the R11/R12 double-buffer attempts that hit the 255-reg cap).
//  - thread = 8 rows x 2 contiguous cols; xq = 128 regs; xj via 8x LDG.128 from
//    L2-resident pre-transposed g_xt; barrier-free mainloop; h fp16 in smem;
//    T=128, 2 CTAs/SM; 3 syncthreads total; streaming STG.128 out.

#define BB 8
#define NN 4096
#define FF 16
#define RR 8
#define TT 128
#define NK 16                     // k-steps of 256 cols (2 per thread)
#define L2E  1.4426950408889634f
#define C528 0.5287663729448977f  // log2(log2(e))

typedef unsigned long long ull;

__device__ float g_sqc[BB * NN];      // cexp * ||x_j||^2
__device__ float g_xt[BB * FF * NN];  // [b][fp][j] float2

// smem: hbuf uint[8][2048] = 64KB (uint m = cols 2m,2m+1), part, inv
#define HBUF_OFF 0
#define PART_OFF 65536
#define INV_OFF  (PART_OFF + 128)
#define SMEM_TOTAL (INV_OFF + 32)

__device__ __forceinline__ ull ffma2(ull a, ull b, ull c) {
    ull d; asm("fma.rn.f32x2 %0, %1, %2, %3;" : "=l"(d) : "l"(a), "l"(b), "l"(c)); return d;
}
__device__ __forceinline__ float2 upk(ull v) {
    float2 r; asm("mov.b64 {%0, %1}, %2;" : "=f"(r.x), "=f"(r.y) : "l"(v)); return r;
}
__device__ __forceinline__ float ex2f(float x) {
    float r; asm("ex2.approx.f32 %0, %1;" : "=f"(r) : "f"(x)); return r;
}
__device__ __forceinline__ unsigned pkh2(float a, float b) {
    __half2 h = __floats2half2_rn(a, b);
    return *reinterpret_cast<unsigned*>(&h);
}
__device__ __forceinline__ void stcs4(float* p, float4 v) {
    asm volatile("st.global.cs.v4.f32 [%0], {%1, %2, %3, %4};"
                 :: "l"(p), "f"(v.x), "f"(v.y), "f"(v.z), "f"(v.w) : "memory");
}
__device__ __forceinline__ ulonglong2 ldg_nc128(const ulonglong2* p) {
    ulonglong2 v;
    asm("ld.global.nc.v2.b64 {%0, %1}, [%2];" : "=l"(v.x), "=l"(v.y) : "l"(p));
    return v;
}

// ---- pre-kernel: transpose X into f-pair rows + cexp*||x_j||^2 ----
__global__ void __launch_bounds__(256)
prep_kernel(const float* __restrict__ X, const float* __restrict__ sigma) {
    int idx = blockIdx.x * 256 + threadIdx.x;          // b*4096 + j
    int b = idx >> 12, j = idx & 4095;
    const float4* p = reinterpret_cast<const float4*>(X) + (size_t)idx * 4;
    float s = 0.f;
    float2* xtb = reinterpret_cast<float2*>(&g_xt[b * 65536]) + j;
    #pragma unroll
    for (int q = 0; q < 4; ++q) {
        float4 v = p[q];
        s += v.x * v.x + v.y * v.y + v.z * v.z + v.w * v.w;
        xtb[(2 * q + 0) * 4096] = make_float2(v.x, v.y);
        xtb[(2 * q + 1) * 4096] = make_float2(v.z, v.w);
    }
    g_sqc[idx] = (-L2E / sigma[0]) * s;
}

__global__ void __launch_bounds__(TT, 2)
GaussianSoftmax_67714454389333_kernel(const float* __restrict__ X,
                                      const float* __restrict__ sigma,
                                      float* __restrict__ out) {
    extern __shared__ char smem_raw[];
    unsigned* hbuf = reinterpret_cast<unsigned*>(smem_raw + HBUF_OFF);  // [8][2048]

    const int tid = threadIdx.x;
    const int b = blockIdx.y;
    const int i0 = blockIdx.x * RR;

    const float* Xb = X + (size_t)b * NN * FF;

    const float sg = sigma[0];
    const float cexp = -L2E / sg;
    const float CM2s = -2.0f * cexp;

    // ---- xq: f-paired xi in regs for ALL 8 rows (128 regs) + sic ----
    ull xq[8][RR];
    float sic[RR];
    #pragma unroll
    for (int r = 0; r < RR; ++r) {
        float s = 0.f;
        #pragma unroll
        for (int fp = 0; fp < 8; ++fp) {
            float2 v = *reinterpret_cast<const float2*>(
                &Xb[(size_t)(i0 + r) * FF + fp * 2]);
            s = fmaf(v.x, v.x, s);
            s = fmaf(v.y, v.y, s);
            xq[fp][r] = *reinterpret_cast<const ull*>(&v);
        }
        sic[r] = fmaf(cexp, s, C528);
    }

    // xt viewed as ulonglong2[fp][2048] per batch: one LDG.128 = 2 cols x 1 f-pair
    const ulonglong2* xt2 =
        reinterpret_cast<const ulonglong2*>(g_xt) + (size_t)b * 16384;
    const float2* sq2 = reinterpret_cast<const float2*>(g_sqc) + b * 2048;

    float rsum[RR];
    #pragma unroll
    for (int r = 0; r < RR; ++r) rsum[r] = 0.f;

    // ---- prologue: loads(0) + dot(0) ----
    ulonglong2 buf[8];
    #pragma unroll
    for (int fp = 0; fp < 8; ++fp)
        buf[fp] = ldg_nc128(xt2 + fp * 2048 + tid);
    float2 sj = __ldg(sq2 + tid);

    ull accA[RR], accB[RR];
    #pragma unroll
    for (int r = 0; r < RR; ++r) { accA[r] = 0; accB[r] = 0; }
    #pragma unroll
    for (int fp = 0; fp < 8; ++fp) {
        ulonglong2 xj = buf[fp];
        #pragma unroll
        for (int r = 0; r < RR; ++r) {
            accA[r] = ffma2(xj.x, xq[fp][r], accA[r]);
            accB[r] = ffma2(xj.y, xq[fp][r], accB[r]);
        }
    }
    float2 sjP = sj;

    // ---- rotated mainloop: loads(k) -> epilogue(k-1) -> dot(k) ----
    #pragma unroll 1
    for (int k = 1; k < NK; ++k) {
        const int m = k * 128 + tid;

        // issue loads for step k (land while the epilogue below runs)
        #pragma unroll
        for (int fp = 0; fp < 8; ++fp)
            buf[fp] = ldg_nc128(xt2 + fp * 2048 + m);
        sj = __ldg(sq2 + m);

        // epilogue for step k-1 (covers the load latency; no dep on buf)
        const int mp = m - 128;
        #pragma unroll
        for (int r = 0; r < RR; ++r) {
            float base = sic[r];
            float2 aA = upk(accA[r]);
            float2 aB = upk(accB[r]);
            float eA = fmaf(CM2s, aA.x + aA.y, base + sjP.x);
            float eB = fmaf(CM2s, aB.x + aB.y, base + sjP.y);
            float hA = ex2f(ex2f(eA));
            float hB = ex2f(ex2f(eB));
            rsum[r] += hA + hB;
            hbuf[r * 2048 + mp] = pkh2(hA, hB);   // cols 2mp, 2mp+1
        }

        // dot for step k
        #pragma unroll
        for (int r = 0; r < RR; ++r) { accA[r] = 0; accB[r] = 0; }
        #pragma unroll
        for (int fp = 0; fp < 8; ++fp) {
            ulonglong2 xj = buf[fp];
            #pragma unroll
            for (int r = 0; r < RR; ++r) {
                accA[r] = ffma2(xj.x, xq[fp][r], accA[r]);
                accB[r] = ffma2(xj.y, xq[fp][r], accB[r]);
            }
        }
        sjP = sj;
    }

    // ---- tail epilogue (step NK-1) ----
    {
        const int mp = (NK - 1) * 128 + tid;
        #pragma unroll
        for (int r = 0; r < RR; ++r) {
            float base = sic[r];
            float2 aA = upk(accA[r]);
            float2 aB = upk(accB[r]);
            float eA = fmaf(CM2s, aA.x + aA.y, base + sjP.x);
            float eB = fmaf(CM2s, aB.x + aB.y, base + sjP.y);
            float hA = ex2f(ex2f(eA));
            float hB = ex2f(ex2f(eB));
            rsum[r] += hA + hB;
            hbuf[r * 2048 + mp] = pkh2(hA, hB);
        }
    }

    // ---- row-sum reduction (4 warps) ----
    float* part = reinterpret_cast<float*>(smem_raw + PART_OFF);   // [4][8]
    #pragma unroll
    for (int r = 0; r < RR; ++r) {
        float v = rsum[r];
        v += __shfl_xor_sync(0xffffffffu, v, 16);
        v += __shfl_xor_sync(0xffffffffu, v, 8);
        v += __shfl_xor_sync(0xffffffffu, v, 4);
        v += __shfl_xor_sync(0xffffffffu, v, 2);
        v += __shfl_xor_sync(0xffffffffu, v, 1);
        if ((tid & 31) == 0) part[(tid >> 5) * 8 + r] = v;
    }
    __syncthreads();
    float* invp = reinterpret_cast<float*>(smem_raw + INV_OFF);
    if (tid < RR) {
        float s = part[0 * 8 + tid] + part[1 * 8 + tid] +
                  part[2 * 8 + tid] + part[3 * 8 + tid];
        invp[tid] = 1.0f / s;
    }
    __syncthreads();

    // ---- phase 2: normalize fp16 h -> two STG.128 per uint4 (8 contig cols) ----
    float* outB = out + ((size_t)b * NN + i0) * NN;
    const uint4* h4 = reinterpret_cast<const uint4*>(hbuf);        // [8][512]
    #pragma unroll 4
    for (int it = 0; it < 32; ++it) {
        int c4 = it * TT + tid;          // 0..4095
        int r = c4 >> 9;
        int w = c4 & 511;                // 8-col group within row
        float inv = invp[r];
        uint4 v = h4[c4];
        float2 p0 = __half22float2(*reinterpret_cast<__half2*>(&v.x));
        float2 p1 = __half22float2(*reinterpret_cast<__half2*>(&v.y));
        float2 p2 = __half22float2(*reinterpret_cast<__half2*>(&v.z));
        float2 p3 = __half22float2(*reinterpret_cast<__half2*>(&v.w));
        float4 oA = make_float4(p0.x * inv, p0.y * inv, p1.x * inv, p1.y * inv);
        float4 oB = make_float4(p2.x * inv, p2.y * inv, p3.x * inv, p3.y * inv);
        float* po = outB + (size_t)r * NN + w * 8;
        stcs4(po, oA);
        stcs4(po + 4, oB);
    }
}

extern "C" void kernel_launch(void* const* d_in, const int* in_sizes, int n_in,
                              void* d_out, int out_size) {
    const float* X = (const float*)d_in[0];
    const float* sigma = (const float*)d_in[1];
    float* out = (float*)d_out;

    prep_kernel<<<BB * NN / 256, 256>>>(X, sigma);

    cudaFuncSetAttribute(GaussianSoftmax_67714454389333_kernel,
                         cudaFuncAttributeMaxDynamicSharedMemorySize, SMEM_TOTAL);
    dim3 grid(NN / RR, BB);   // (512, 8)
    GaussianSoftmax_67714454389333_kernel<<<grid, TT, SMEM_TOTAL>>>(X, sigma, out);
}